// round 2
// baseline (speedup 1.0000x reference)
#include <cuda_runtime.h>
#include <cstdint>
#include <cstddef>

#define C_IN 256
#define HW 128
#define IMG (HW*HW)
#define KC 8
#define AS_STRIDE 520   // % 32 == 8 -> conflict-free
#define BS_STRIDE 72
#define NTAP 5
#define NGROUP 4

// Binarized weights [g][tap][c][co], +-1.0f
__device__ float g_wsgn[NGROUP*NTAP*C_IN*64];

__global__ void prep_weights(const float* __restrict__ w1, const float* __restrict__ w2,
                             const float* __restrict__ w3, const float* __restrict__ w4) {
    int idx = blockIdx.x * blockDim.x + threadIdx.x;
    if (idx >= NGROUP*NTAP*C_IN*64) return;
    int g   = idx / (NTAP*C_IN*64);
    int rem = idx % (NTAP*C_IN*64);
    int t   = rem / (C_IN*64);
    int c   = (rem / 64) % C_IN;
    int co  = rem % 64;
    const float* w = (g==0) ? w1 : (g==1) ? w2 : (g==2) ? w3 : w4;
    float v = w[((size_t)co*C_IN + c)*NTAP + t];
    g_wsgn[idx] = (v < 0.f) ? -1.f : 1.f;
}

__device__ __forceinline__ float to_tf32(float v) {
    uint32_t u;
    asm volatile("cvt.rna.tf32.f32 %0, %1;" : "=r"(u) : "f"(v));
    return __uint_as_float(u);
}

#define MMA_TF32(cd, A0,A1,A2,A3, B0,B1)                                     \
  asm volatile("mma.sync.aligned.m16n8k8.row.col.f32.tf32.tf32.f32 "         \
    "{%0,%1,%2,%3},{%4,%5,%6,%7},{%8,%9},{%0,%1,%2,%3};\n"                   \
    : "+f"(cd[0]), "+f"(cd[1]), "+f"(cd[2]), "+f"(cd[3])                     \
    : "r"(A0), "r"(A1), "r"(A2), "r"(A3), "r"(B0), "r"(B1))

// One CTA: M=256 pixels x N=64 co x K=1280. grid=(1024 tiles, 4 groups).
// 256 threads = 8 warps (4 M x 2 N), warp tile 64x32.
__global__ __launch_bounds__(256, 1) void mrb_conv_kernel(
    const float* __restrict__ x,
    const float* __restrict__ bb1, const float* __restrict__ bb2,
    const float* __restrict__ bb3, const float* __restrict__ bb4,
    float* __restrict__ out)
{
    __shared__ float As[KC * AS_STRIDE];
    __shared__ float Bs[NTAP * KC * BS_STRIDE];

    const int g    = blockIdx.y;     // 0:(1,5)d1 1:(1,5)d2 2:(5,1)d1 3:(5,1)d2
    const bool vert = (g >= 2);
    const bool dil2 = (g & 1);
    const int tile = blockIdx.x;
    const int n = tile >> 6;
    int h0, w0 = 0;
    if (!vert) {
        h0 = (tile & 63) * 2;                       // 2 rows x 128 w
    } else {
        int r = tile & 63;
        h0 = (r >> 2) * 8;  w0 = (r & 3) * 32;      // 8 h x 32 w
    }

    const float* xb = x + (size_t)n * C_IN * IMG;

    const int tid  = threadIdx.x;
    const int lane = tid & 31, warp = tid >> 5;
    const int wm = warp >> 1, wn = warp & 1;
    const int qrow = lane >> 2, qcol = lane & 3;

    float acc[4][4][4];
    #pragma unroll
    for (int i = 0; i < 4; i++)
        #pragma unroll
        for (int j = 0; j < 4; j++)
            #pragma unroll
            for (int r = 0; r < 4; r++) acc[i][j][r] = 0.f;

    // A-fragment base offsets within a channel row, for m-row qrow and qrow+8
    int offA[4][2];
    #pragma unroll
    for (int mt = 0; mt < 4; mt++) {
        #pragma unroll
        for (int hh = 0; hh < 2; hh++) {
            int mm = wm*64 + mt*16 + qrow + hh*8;
            offA[mt][hh] = vert ? (((mm >> 5) + 4) * 32 + (mm & 31))
                                : ((mm >> 7) * 136 + (mm & 127) + 4);
        }
    }

    // Pre-zero w-halo (horizontal tiles); never rewritten by chunk loop
    if (!vert && tid < KC * 16) {
        int c = tid >> 4, s = tid & 15, r = s >> 3, j = s & 7;
        As[c*AS_STRIDE + r*136 + (j < 4 ? j : 128 + j)] = 0.f;
    }

    float ra[16];
    float rb[2*NTAP];
    const int cA = tid >> 5, sA = tid & 31;   // 8 channels, 32 threads each

    auto loadA = [&](int q) {
        int c0 = q * KC;
        if (!vert) {
            int r = sA >> 4, wb = (sA & 15) * 8;
            const float4* p4 = reinterpret_cast<const float4*>(
                xb + (size_t)(c0 + cA) * IMG + (h0 + r) * HW + wb);
            float4 v0 = p4[0], v1 = p4[1];
            ra[0]=to_tf32(v0.x); ra[1]=to_tf32(v0.y); ra[2]=to_tf32(v0.z); ra[3]=to_tf32(v0.w);
            ra[4]=to_tf32(v1.x); ra[5]=to_tf32(v1.y); ra[6]=to_tf32(v1.z); ra[7]=to_tf32(v1.w);
        } else {
            int hl = sA >> 1, wb = (sA & 1) * 16;
            int row = h0 - 4 + hl;
            if ((unsigned)row < (unsigned)HW) {
                const float4* p4 = reinterpret_cast<const float4*>(
                    xb + (size_t)(c0 + cA) * IMG + row * HW + w0 + wb);
                #pragma unroll
                for (int j = 0; j < 4; j++) {
                    float4 v = p4[j];
                    ra[4*j+0]=to_tf32(v.x); ra[4*j+1]=to_tf32(v.y);
                    ra[4*j+2]=to_tf32(v.z); ra[4*j+3]=to_tf32(v.w);
                }
            } else {
                #pragma unroll
                for (int j = 0; j < 16; j++) ra[j] = 0.f;
            }
        }
    };

    auto storeA = [&]() {
        if (!vert) {
            int r = sA >> 4, wb = (sA & 15) * 8;
            float* d = As + cA*AS_STRIDE + r*136 + 4 + wb;
            reinterpret_cast<float4*>(d)[0] = make_float4(ra[0], ra[1], ra[2], ra[3]);
            reinterpret_cast<float4*>(d)[1] = make_float4(ra[4], ra[5], ra[6], ra[7]);
        } else {
            int hl = sA >> 1, wb = (sA & 1) * 16;
            float* d = As + cA*AS_STRIDE + hl*32 + wb;
            #pragma unroll
            for (int j = 0; j < 4; j++)
                reinterpret_cast<float4*>(d)[j] =
                    make_float4(ra[4*j+0], ra[4*j+1], ra[4*j+2], ra[4*j+3]);
        }
    };

    auto loadB = [&](int q) {
        int c0 = q * KC;
        const float* wp = g_wsgn + ((size_t)(g*NTAP) * C_IN + c0 + cA) * 64 + sA * 2;
        #pragma unroll
        for (int t = 0; t < NTAP; t++) {
            float2 v = *reinterpret_cast<const float2*>(wp + (size_t)t * C_IN * 64);
            rb[2*t] = v.x;  rb[2*t+1] = v.y;
        }
    };

    auto storeB = [&]() {
        #pragma unroll
        for (int t = 0; t < NTAP; t++)
            *reinterpret_cast<float2*>(Bs + (t*KC + cA) * BS_STRIDE + sA * 2) =
                make_float2(rb[2*t], rb[2*t+1]);
    };

    loadA(0); loadB(0);
    const int NCHUNK = C_IN / KC;
    for (int q = 0; q < NCHUNK; q++) {
        __syncthreads();
        storeA(); storeB();
        __syncthreads();
        if (q + 1 < NCHUNK) { loadA(q + 1); loadB(q + 1); }  // LDG overlaps MMA

        const uint32_t* AsU = reinterpret_cast<const uint32_t*>(As);
        const uint32_t* BsU = reinterpret_cast<const uint32_t*>(Bs);
        #pragma unroll
        for (int t = 0; t < NTAP; t++) {
            int d  = dil2 ? (2*t - 4) : (t - 2);
            int sh = vert ? d * 32 : d;          // tap = pixel shift of A fragment
            uint32_t b0[4], b1[4];
            #pragma unroll
            for (int nt = 0; nt < 4; nt++) {
                int col = wn*32 + nt*8 + qrow;
                b0[nt] = BsU[(t*KC + qcol    ) * BS_STRIDE + col];
                b1[nt] = BsU[(t*KC + qcol + 4) * BS_STRIDE + col];
            }
            #pragma unroll
            for (int mt = 0; mt < 4; mt++) {
                uint32_t a0 = AsU[ qcol      * AS_STRIDE + offA[mt][0] + sh];
                uint32_t a1 = AsU[ qcol      * AS_STRIDE + offA[mt][1] + sh];
                uint32_t a2 = AsU[(qcol + 4) * AS_STRIDE + offA[mt][0] + sh];
                uint32_t a3 = AsU[(qcol + 4) * AS_STRIDE + offA[mt][1] + sh];
                #pragma unroll
                for (int nt = 0; nt < 4; nt++)
                    MMA_TF32(acc[mt][nt], a0, a1, a2, a3, b0[nt], b1[nt]);
            }
        }
    }

    // Epilogue: bias + store
    const float* bias = (g==0) ? bb1 : (g==1) ? bb2 : (g==2) ? bb3 : bb4;
    float* ob = out + ((size_t)n * 256 + g * 64) * IMG;
    #pragma unroll
    for (int nt = 0; nt < 4; nt++) {
        #pragma unroll
        for (int r = 0; r < 4; r++) {
            int co = wn*32 + nt*8 + 2*qcol + (r & 1);
            float bv = bias[co];
            #pragma unroll
            for (int mt = 0; mt < 4; mt++) {
                int m = wm*64 + mt*16 + qrow + ((r >> 1) << 3);
                int pix = vert ? ((h0 + (m >> 5)) * HW + w0 + (m & 31))
                               : ((h0 + (m >> 7)) * HW + (m & 127));
                ob[(size_t)co * IMG + pix] = acc[mt][nt][r] + bv;
            }
        }
    }
}

extern "C" void kernel_launch(void* const* d_in, const int* in_sizes, int n_in,
                              void* d_out, int out_size) {
    const float* x  = (const float*)d_in[0];
    const float* w1 = (const float*)d_in[1];
    const float* b1 = (const float*)d_in[2];
    const float* w2 = (const float*)d_in[3];
    const float* b2 = (const float*)d_in[4];
    const float* w3 = (const float*)d_in[5];
    const float* b3 = (const float*)d_in[6];
    const float* w4 = (const float*)d_in[7];
    const float* b4 = (const float*)d_in[8];
    float* out = (float*)d_out;

    prep_weights<<<(NGROUP*NTAP*C_IN*64 + 255)/256, 256>>>(w1, w2, w3, w4);
    dim3 grid(16 * 64, NGROUP);
    mrb_conv_kernel<<<grid, 256>>>(x, b1, b2, b3, b4, out);
}

// round 3
// speedup vs baseline: 1.5253x; 1.5253x over previous
#include <cuda_runtime.h>
#include <cstdint>
#include <cstddef>

#define C_IN 256
#define HW 128
#define IMG (HW*HW)
#define KC 8
#define AS_H_ST 136       // horizontal: 4 halo + 128 + 4 halo, 136 % 32 == 8
#define AS_V_ST 264       // vertical: 16 rows x 16 w = 256, padded to 264 (% 32 == 8)
#define BS_STRIDE 72      // 72 % 32 == 8
#define NTAP 5
#define NGROUP 4

// Binarized weights [g][tap][c][co], +-1.0f
__device__ float g_wsgn[NGROUP*NTAP*C_IN*64];

__global__ void prep_weights(const float* __restrict__ w1, const float* __restrict__ w2,
                             const float* __restrict__ w3, const float* __restrict__ w4) {
    int idx = blockIdx.x * blockDim.x + threadIdx.x;
    if (idx >= NGROUP*NTAP*C_IN*64) return;
    int g   = idx / (NTAP*C_IN*64);
    int rem = idx % (NTAP*C_IN*64);
    int t   = rem / (C_IN*64);
    int c   = (rem / 64) % C_IN;
    int co  = rem % 64;
    const float* w = (g==0) ? w1 : (g==1) ? w2 : (g==2) ? w3 : w4;
    float v = w[((size_t)co*C_IN + c)*NTAP + t];
    g_wsgn[idx] = (v < 0.f) ? -1.f : 1.f;
}

#define MMA_TF32(cd, A0,A1,A2,A3, B0,B1)                                     \
  asm volatile("mma.sync.aligned.m16n8k8.row.col.f32.tf32.tf32.f32 "         \
    "{%0,%1,%2,%3},{%4,%5,%6,%7},{%8,%9},{%0,%1,%2,%3};\n"                   \
    : "+f"(cd[0]), "+f"(cd[1]), "+f"(cd[2]), "+f"(cd[3])                     \
    : "r"(A0), "r"(A1), "r"(A2), "r"(A3), "r"(B0), "r"(B1))

__device__ __forceinline__ void cp_async16(uint32_t dst, const void* src, int src_bytes) {
    asm volatile("cp.async.cg.shared.global [%0], [%1], 16, %2;\n"
                 :: "r"(dst), "l"(src), "r"(src_bytes));
}
__device__ __forceinline__ void cp_commit()  { asm volatile("cp.async.commit_group;\n"); }
__device__ __forceinline__ void cp_wait0()   { asm volatile("cp.async.wait_group 0;\n"); }

// CTA: M=128 pixels x N=64 co x K=1280 (256 ch * 5 taps).
// 128 threads = 4 warps (2M x 2N), warp tile 64x32. Double-buffered cp.async.
__global__ __launch_bounds__(128, 3) void mrb_conv_kernel(
    const float* __restrict__ x,
    const float* __restrict__ bb1, const float* __restrict__ bb2,
    const float* __restrict__ bb3, const float* __restrict__ bb4,
    float* __restrict__ out)
{
    __shared__ float As[2][KC * AS_V_ST];            // 2 x 8.25KB
    __shared__ float Bs[2][NTAP * KC * BS_STRIDE];   // 2 x 11.25KB

    const int g    = blockIdx.y;     // 0:(1,5)d1 1:(1,5)d2 2:(5,1)d1 3:(5,1)d2
    const bool vert = (g >= 2);
    const bool dil2 = (g & 1);
    const int tile = blockIdx.x;     // 128 tiles per image
    const int n = tile >> 7;
    int h0, w0 = 0;
    if (!vert) {
        h0 = tile & 127;                            // 1 row x 128 w
    } else {
        int r = tile & 127;
        h0 = (r >> 3) * 8;  w0 = (r & 7) * 16;      // 8 h x 16 w
    }
    const int AS_ST = vert ? AS_V_ST : AS_H_ST;

    const float* xb = x + (size_t)n * C_IN * IMG;

    const int tid  = threadIdx.x;
    const int lane = tid & 31, warp = tid >> 5;
    const int wm = warp >> 1, wn = warp & 1;
    const int qrow = lane >> 2, qcol = lane & 3;

    float acc[4][4][4];
    #pragma unroll
    for (int i = 0; i < 4; i++)
        #pragma unroll
        for (int j = 0; j < 4; j++)
            #pragma unroll
            for (int r = 0; r < 4; r++) acc[i][j][r] = 0.f;

    // A-fragment base offsets within a channel block (m-rows qrow and qrow+8)
    int offA[4][2];
    #pragma unroll
    for (int mt = 0; mt < 4; mt++) {
        #pragma unroll
        for (int hh = 0; hh < 2; hh++) {
            int mm = wm*64 + mt*16 + qrow + hh*8;   // 0..127
            offA[mt][hh] = vert ? (((mm >> 4) + 4) * 16 + (mm & 15))
                                : (4 + mm);
        }
    }

    const uint32_t asBase0 = (uint32_t)__cvta_generic_to_shared(&As[0][0]);
    const uint32_t asBase1 = (uint32_t)__cvta_generic_to_shared(&As[1][0]);
    const uint32_t bsBase0 = (uint32_t)__cvta_generic_to_shared(&Bs[0][0]);
    const uint32_t bsBase1 = (uint32_t)__cvta_generic_to_shared(&Bs[1][0]);

    // Pre-zero the horizontal w-halo in both buffers (always zero; never rewritten)
    if (!vert) {   // 8 ch * 8 floats * 2 buffers = 128 writes, one per thread
        int buf = tid >> 6, ch = (tid >> 3) & 7, j = tid & 7;
        As[buf][ch*AS_H_ST + (j < 4 ? j : 128 + j)] = 0.f;
    }

    // issue cp.async copies for chunk q into buffer `buf`
    auto issue = [&](int q, int buf) {
        const uint32_t aB = buf ? asBase1 : asBase0;
        const uint32_t bB = buf ? bsBase1 : bsBase0;
        const int c0 = q * KC;
        if (!vert) {
            // A: 8 ch x 128 w interior; thread -> (ch = tid>>4, s = tid&15), 8 floats
            int ch = tid >> 4, s = tid & 15;
            const float* src = xb + (size_t)(c0 + ch) * IMG + h0 * HW + s * 8;
            uint32_t dst = aB + (ch*AS_H_ST + 4 + s*8) * 4;
            cp_async16(dst,      src,     16);
            cp_async16(dst + 16, src + 4, 16);
        } else {
            // A: 8 ch x 16 rows x 16 w; thread -> (ch = tid>>4, row = tid&15)
            int ch = tid >> 4, rr = tid & 15;
            int row = h0 - 4 + rr;
            int ok = ((unsigned)row < (unsigned)HW) ? 16 : 0;
            int rowc = ok ? row : 0;
            const float* src = xb + (size_t)(c0 + ch) * IMG + rowc * HW + w0;
            uint32_t dst = aB + (ch*AS_V_ST + rr*16) * 4;
            #pragma unroll
            for (int j = 0; j < 4; j++)
                cp_async16(dst + j*16, src + j*4, ok);
        }
        // B: 5 taps x 8 k x 64 co; thread -> (k = tid>>4, co4 = tid&15), one float4/tap
        {
            int k = tid >> 4, co4 = tid & 15;
            const float* srcb = g_wsgn + ((size_t)(g*NTAP) * C_IN + c0 + k) * 64 + co4 * 4;
            #pragma unroll
            for (int t = 0; t < NTAP; t++) {
                uint32_t dst = bB + ((t*KC + k) * BS_STRIDE + co4*4) * 4;
                cp_async16(dst, srcb + (size_t)t * C_IN * 64, 16);
            }
        }
        cp_commit();
    };

    issue(0, 0);
    const int NCHUNK = C_IN / KC;
    for (int q = 0; q < NCHUNK; q++) {
        cp_wait0();
        __syncthreads();                 // chunk q visible; all warps past chunk q-1 MMAs
        if (q + 1 < NCHUNK) issue(q + 1, (q + 1) & 1);   // overlaps MMAs below

        const uint32_t* AsU = reinterpret_cast<const uint32_t*>(&As[q & 1][0]);
        const uint32_t* BsU = reinterpret_cast<const uint32_t*>(&Bs[q & 1][0]);
        #pragma unroll
        for (int t = 0; t < NTAP; t++) {
            int d  = dil2 ? (2*t - 4) : (t - 2);
            int sh = vert ? d * 16 : d;          // tap = pixel shift of A fragment
            uint32_t b0[4], b1[4];
            #pragma unroll
            for (int nt = 0; nt < 4; nt++) {
                int col = wn*32 + nt*8 + qrow;
                b0[nt] = BsU[(t*KC + qcol    ) * BS_STRIDE + col];
                b1[nt] = BsU[(t*KC + qcol + 4) * BS_STRIDE + col];
            }
            #pragma unroll
            for (int mt = 0; mt < 4; mt++) {
                uint32_t a0 = AsU[ qcol      * AS_ST + offA[mt][0] + sh];
                uint32_t a1 = AsU[ qcol      * AS_ST + offA[mt][1] + sh];
                uint32_t a2 = AsU[(qcol + 4) * AS_ST + offA[mt][0] + sh];
                uint32_t a3 = AsU[(qcol + 4) * AS_ST + offA[mt][1] + sh];
                #pragma unroll
                for (int nt = 0; nt < 4; nt++)
                    MMA_TF32(acc[mt][nt], a0, a1, a2, a3, b0[nt], b1[nt]);
            }
        }
    }

    // Epilogue: bias + store
    const float* bias = (g==0) ? bb1 : (g==1) ? bb2 : (g==2) ? bb3 : bb4;
    float* ob = out + ((size_t)n * 256 + g * 64) * IMG;
    #pragma unroll
    for (int nt = 0; nt < 4; nt++) {
        #pragma unroll
        for (int r = 0; r < 4; r++) {
            int co = wn*32 + nt*8 + 2*qcol + (r & 1);
            float bv = bias[co];
            #pragma unroll
            for (int mt = 0; mt < 4; mt++) {
                int m = wm*64 + mt*16 + qrow + ((r >> 1) << 3);
                int pix = vert ? ((h0 + (m >> 4)) * HW + w0 + (m & 15))
                               : (h0 * HW + m);
                ob[(size_t)co * IMG + pix] = acc[mt][nt][r] + bv;
            }
        }
    }
}

extern "C" void kernel_launch(void* const* d_in, const int* in_sizes, int n_in,
                              void* d_out, int out_size) {
    const float* x  = (const float*)d_in[0];
    const float* w1 = (const float*)d_in[1];
    const float* b1 = (const float*)d_in[2];
    const float* w2 = (const float*)d_in[3];
    const float* b2 = (const float*)d_in[4];
    const float* w3 = (const float*)d_in[5];
    const float* b3 = (const float*)d_in[6];
    const float* w4 = (const float*)d_in[7];
    const float* b4 = (const float*)d_in[8];
    float* out = (float*)d_out;

    prep_weights<<<(NGROUP*NTAP*C_IN*64 + 255)/256, 256>>>(w1, w2, w3, w4);
    dim3 grid(16 * 128, NGROUP);
    mrb_conv_kernel<<<grid, 128>>>(x, b1, b2, b3, b4, out);
}

// round 6
// speedup vs baseline: 2.6474x; 1.7357x over previous
#include <cuda_runtime.h>
#include <cuda_fp16.h>
#include <cstdint>
#include <cstddef>

#define C_IN 256
#define HW 128
#define IMG (HW*HW)
#define KC 8              // k2-rows (half2 channel-pairs) per chunk = 16 channels
#define NCHUNK 16
#define AS_H_ST 136       // elements: 4 halo + 128 + 4 halo  (% 32 == 8)
#define AS_V_ST 264       // elements: 16 rows x 16 w + pad    (% 32 == 8)
#define BS_STRIDE 72      // % 32 == 8
#define NTAP 5
#define NGROUP 4

// x converted to half2 channel-pairs: [img][c2(128)][pix], element = half2(c even, c odd)
__device__ uint32_t g_xh[(size_t)16*128*IMG];           // 128 MB
// binarized weights, half2 channel-pairs: [g][t][k2(128)][co(64)]
__device__ uint32_t g_wb[NGROUP*NTAP*128*64];

__global__ void prep_weights(const float* __restrict__ w1, const float* __restrict__ w2,
                             const float* __restrict__ w3, const float* __restrict__ w4) {
    int idx = blockIdx.x * blockDim.x + threadIdx.x;
    if (idx >= NGROUP*NTAP*128*64) return;
    int n   = idx & 63;
    int k2  = (idx >> 6) & 127;
    int gt  = idx >> 13;              // g*5 + t
    int t = gt % 5, g = gt / 5;
    int c0 = 2*k2;
    const float* w = g==0?w1:g==1?w2:g==2?w3:w4;
    float v0 = w[((size_t)n*C_IN + c0    )*NTAP + t];
    float v1 = w[((size_t)n*C_IN + c0 + 1)*NTAP + t];
    uint32_t lo = (v0 < 0.f) ? 0xBC00u : 0x3C00u;     // fp16 -1 / +1
    uint32_t hi = (v1 < 0.f) ? 0xBC00u : 0x3C00u;
    g_wb[idx] = (hi << 16) | lo;
}

// pack half2: lo = a (even channel), hi = b (odd channel)
__device__ __forceinline__ uint32_t pack_h2(float a, float b) {
    uint32_t r;
    asm("cvt.rn.f16x2.f32 %0, %1, %2;" : "=r"(r) : "f"(b), "f"(a));
    return r;
}

// pack x: each thread handles 4 pixels of one channel-pair (uint4 = 4 half2)
__global__ void convert_x(const float* __restrict__ x) {
    size_t i = (size_t)blockIdx.x * blockDim.x + threadIdx.x;   // uint4 index
    // i = ((img*128 + c2)*4096 + pix4)
    int pix4 = (int)(i & 4095);
    int c2   = (int)((i >> 12) & 127);
    int img  = (int)(i >> 19);
    const float4* p0 = reinterpret_cast<const float4*>(
        x + ((size_t)img*C_IN + 2*c2    )*IMG) + pix4;
    const float4* p1 = reinterpret_cast<const float4*>(
        x + ((size_t)img*C_IN + 2*c2 + 1)*IMG) + pix4;
    float4 a = *p0, b = *p1;
    uint4 o;
    o.x = pack_h2(a.x, b.x);
    o.y = pack_h2(a.y, b.y);
    o.z = pack_h2(a.z, b.z);
    o.w = pack_h2(a.w, b.w);
    reinterpret_cast<uint4*>(g_xh)[i] = o;
}

#define MMA_F16(cd, A0,A1,A2,A3, B0,B1)                                      \
  asm volatile("mma.sync.aligned.m16n8k16.row.col.f32.f16.f16.f32 "          \
    "{%0,%1,%2,%3},{%4,%5,%6,%7},{%8,%9},{%0,%1,%2,%3};\n"                   \
    : "+f"(cd[0]), "+f"(cd[1]), "+f"(cd[2]), "+f"(cd[3])                     \
    : "r"(A0), "r"(A1), "r"(A2), "r"(A3), "r"(B0), "r"(B1))

__device__ __forceinline__ void cp_async16(uint32_t dst, const void* src, int src_bytes) {
    asm volatile("cp.async.cg.shared.global [%0], [%1], 16, %2;\n"
                 :: "r"(dst), "l"(src), "r"(src_bytes));
}
__device__ __forceinline__ void cp_commit()  { asm volatile("cp.async.commit_group;\n"); }
__device__ __forceinline__ void cp_wait0()   { asm volatile("cp.async.wait_group 0;\n"); }

// CTA: M=128 pixels x N=64 co x K=1280-equivalent (256 ch * 5 taps), fp16 MMA.
// 128 threads = 4 warps (2M x 2N), warp tile 64x32. Double-buffered cp.async.
__global__ __launch_bounds__(128, 3) void mrb_conv_kernel(
    const float* __restrict__ bb1, const float* __restrict__ bb2,
    const float* __restrict__ bb3, const float* __restrict__ bb4,
    float* __restrict__ out)
{
    __shared__ uint32_t As[2][KC * AS_V_ST];
    __shared__ uint32_t Bs[2][NTAP * KC * BS_STRIDE];

    const int g    = blockIdx.y;     // 0:(1,5)d1 1:(1,5)d2 2:(5,1)d1 3:(5,1)d2
    const bool vert = (g >= 2);
    const bool dil2 = (g & 1);
    const int tile = blockIdx.x;     // 128 tiles per image
    const int n = tile >> 7;
    int h0, w0 = 0;
    if (!vert) {
        h0 = tile & 127;                            // 1 row x 128 w
    } else {
        int r = tile & 127;
        h0 = (r >> 3) * 8;  w0 = (r & 7) * 16;      // 8 h x 16 w
    }
    const int AS_ST = vert ? AS_V_ST : AS_H_ST;

    const uint32_t* xb = g_xh + (size_t)n * 128 * IMG;   // [c2][pix]

    const int tid  = threadIdx.x;
    const int lane = tid & 31, warp = tid >> 5;
    const int wm = warp >> 1, wn = warp & 1;
    const int qrow = lane >> 2, qcol = lane & 3;

    float acc[4][4][4];
    #pragma unroll
    for (int i = 0; i < 4; i++)
        #pragma unroll
        for (int j = 0; j < 4; j++)
            #pragma unroll
            for (int r = 0; r < 4; r++) acc[i][j][r] = 0.f;

    // A-fragment base offsets within a k2 block (m-rows qrow and qrow+8)
    int offA[4][2];
    #pragma unroll
    for (int mt = 0; mt < 4; mt++) {
        #pragma unroll
        for (int hh = 0; hh < 2; hh++) {
            int mm = wm*64 + mt*16 + qrow + hh*8;   // 0..127
            offA[mt][hh] = vert ? (((mm >> 4) + 4) * 16 + (mm & 15))
                                : (4 + mm);
        }
    }

    const uint32_t asBase0 = (uint32_t)__cvta_generic_to_shared(&As[0][0]);
    const uint32_t asBase1 = (uint32_t)__cvta_generic_to_shared(&As[1][0]);
    const uint32_t bsBase0 = (uint32_t)__cvta_generic_to_shared(&Bs[0][0]);
    const uint32_t bsBase1 = (uint32_t)__cvta_generic_to_shared(&Bs[1][0]);

    // Pre-zero the horizontal w-halo in both buffers
    if (!vert) {   // 8 k2 * 8 elements * 2 buffers = 128 writes
        int buf = tid >> 6, ch = (tid >> 3) & 7, j = tid & 7;
        As[buf][ch*AS_H_ST + (j < 4 ? j : 128 + j)] = 0u;
    }

    // issue cp.async copies for chunk q (16 channels = 8 k2-rows) into buffer `buf`
    auto issue = [&](int q, int buf) {
        const uint32_t aB = buf ? asBase1 : asBase0;
        const uint32_t bB = buf ? bsBase1 : bsBase0;
        const int k0 = q * KC;            // k2 base
        if (!vert) {
            // A: 8 k2 x 128 w interior; thread -> (ch = tid>>4, s = tid&15), 8 elems
            int ch = tid >> 4, s = tid & 15;
            const uint32_t* src = xb + (size_t)(k0 + ch) * IMG + h0 * HW + s * 8;
            uint32_t dst = aB + (ch*AS_H_ST + 4 + s*8) * 4;
            cp_async16(dst,      src,     16);
            cp_async16(dst + 16, src + 4, 16);
        } else {
            // A: 8 k2 x 16 rows x 16 w; thread -> (ch = tid>>4, row = tid&15)
            int ch = tid >> 4, rr = tid & 15;
            int row = h0 - 4 + rr;
            int ok = ((unsigned)row < (unsigned)HW) ? 16 : 0;
            int rowc = ok ? row : 0;
            const uint32_t* src = xb + (size_t)(k0 + ch) * IMG + rowc * HW + w0;
            uint32_t dst = aB + (ch*AS_V_ST + rr*16) * 4;
            #pragma unroll
            for (int j = 0; j < 4; j++)
                cp_async16(dst + j*16, src + j*4, ok);
        }
        // B: 5 taps x 8 k2 x 64 co; thread -> (k = tid>>4, co4 = tid&15)
        {
            int k = tid >> 4, co4 = tid & 15;
            const uint32_t* srcb = g_wb + ((size_t)(g*NTAP) * 128 + k0 + k) * 64 + co4 * 4;
            #pragma unroll
            for (int t = 0; t < NTAP; t++) {
                uint32_t dst = bB + ((t*KC + k) * BS_STRIDE + co4*4) * 4;
                cp_async16(dst, srcb + (size_t)t * 128 * 64, 16);
            }
        }
        cp_commit();
    };

    issue(0, 0);
    for (int q = 0; q < NCHUNK; q++) {
        cp_wait0();
        __syncthreads();                 // chunk q visible; all warps past chunk q-1 MMAs
        if (q + 1 < NCHUNK) issue(q + 1, (q + 1) & 1);   // overlaps MMAs below

        const uint32_t* AsU = &As[q & 1][0];
        const uint32_t* BsU = &Bs[q & 1][0];
        #pragma unroll
        for (int t = 0; t < NTAP; t++) {
            int d  = dil2 ? (2*t - 4) : (t - 2);
            int sh = vert ? d * 16 : d;          // tap = pixel shift of A fragment
            uint32_t b0[4], b1[4];
            #pragma unroll
            for (int nt = 0; nt < 4; nt++) {
                int col = wn*32 + nt*8 + qrow;
                b0[nt] = BsU[(t*KC + qcol    ) * BS_STRIDE + col];
                b1[nt] = BsU[(t*KC + qcol + 4) * BS_STRIDE + col];
            }
            #pragma unroll
            for (int mt = 0; mt < 4; mt++) {
                uint32_t a0 = AsU[ qcol      * AS_ST + offA[mt][0] + sh];
                uint32_t a1 = AsU[ qcol      * AS_ST + offA[mt][1] + sh];
                uint32_t a2 = AsU[(qcol + 4) * AS_ST + offA[mt][0] + sh];
                uint32_t a3 = AsU[(qcol + 4) * AS_ST + offA[mt][1] + sh];
                #pragma unroll
                for (int nt = 0; nt < 4; nt++)
                    MMA_F16(acc[mt][nt], a0, a1, a2, a3, b0[nt], b1[nt]);
            }
        }
    }

    // Epilogue: bias + store
    const float* bias = (g==0) ? bb1 : (g==1) ? bb2 : (g==2) ? bb3 : bb4;
    float* ob = out + ((size_t)n * 256 + g * 64) * IMG;
    #pragma unroll
    for (int nt = 0; nt < 4; nt++) {
        #pragma unroll
        for (int r = 0; r < 4; r++) {
            int co = wn*32 + nt*8 + 2*qcol + (r & 1);
            float bv = bias[co];
            #pragma unroll
            for (int mt = 0; mt < 4; mt++) {
                int m = wm*64 + mt*16 + qrow + ((r >> 1) << 3);
                int pix = vert ? ((h0 + (m >> 4)) * HW + w0 + (m & 15))
                               : (h0 * HW + m);
                ob[(size_t)co * IMG + pix] = acc[mt][nt][r] + bv;
            }
        }
    }
}

extern "C" void kernel_launch(void* const* d_in, const int* in_sizes, int n_in,
                              void* d_out, int out_size) {
    const float* x  = (const float*)d_in[0];
    const float* w1 = (const float*)d_in[1];
    const float* b1 = (const float*)d_in[2];
    const float* w2 = (const float*)d_in[3];
    const float* b2 = (const float*)d_in[4];
    const float* w3 = (const float*)d_in[5];
    const float* b3 = (const float*)d_in[6];
    const float* w4 = (const float*)d_in[7];
    const float* b4 = (const float*)d_in[8];
    float* out = (float*)d_out;

    prep_weights<<<(NGROUP*NTAP*128*64 + 255)/256, 256>>>(w1, w2, w3, w4);
    convert_x<<<(int)(((size_t)16*128*IMG/4) / 256), 256>>>(x);
    dim3 grid(16 * 128, NGROUP);
    mrb_conv_kernel<<<grid, 128>>>(b1, b2, b3, b4, out);
}